// round 10
// baseline (speedup 1.0000x reference)
#include <cuda_runtime.h>
#include <cuda_fp16.h>

#define B    512
#define L    32768
#define WSZ  100                 // WINDOW*3 - 2
#define NOUT (L - WSZ + 1)       // 32669
#define TPB  128
#define KPT  32
#define CHUNK (TPB * KPT)        // 4096 outputs per block
#define NCHUNK 8                 // ceil(NOUT/CHUNK)
#define STAGE (CHUNK + WSZ - 1)  // 4195 staged inputs
#define GROUPS 64
#define ROWS_PER_G (B / GROUPS)  // 8

// float staging: pad every 32 -> stride-32 accesses conflict-free
#define IX(i)  ((i) + ((i) >> 5))
#define SPAD   (STAGE + (STAGE >> 5) + 4)
// half result staging: pad every 16 -> stride-32 STS.16 lands on banks 17t mod 32 (conflict-free)
#define IXH(i) ((i) + ((i) >> 4))
#define HPAD   (CHUNK + (CHUNK >> 4) + 4)

#define TOTAL ((size_t)B * NOUT)

// Scratch (static device arrays)
__device__ __half g_corr_h[TOTAL];
__device__ float  g_partial[GROUPS * NOUT];
__device__ float  g_avg[NOUT];

// K1: windowed correlation for 8 rows per block + fused column partial sums.
__global__ __launch_bounds__(TPB) void corr_fused_kernel(const float* __restrict__ x) {
    __shared__ float  sa[SPAD];
    __shared__ float  sb[SPAD];
    __shared__ __half rs[HPAD];

    const int grp = blockIdx.y;
    const int c0  = blockIdx.x * CHUNK;
    const int base = threadIdx.x * KPT;
    const float invw = 1.0f / (float)WSZ;

    float acc[KPT];
    #pragma unroll
    for (int k = 0; k < KPT; k++) acc[k] = 0.f;

    for (int r = 0; r < ROWS_PER_G; r++) {
        const int row = grp * ROWS_PER_G + r;
        const float* __restrict__ x1 = x + (size_t)row * (2 * L);
        const float* __restrict__ x2 = x1 + L;

        // ---- stage (float4 fast path, scalar guarded tail) ----
        for (int i4 = threadIdx.x * 4; i4 < STAGE; i4 += TPB * 4) {
            int idx = c0 + i4;
            if (i4 + 3 < STAGE && idx + 3 < L) {
                float4 va = *reinterpret_cast<const float4*>(x1 + idx);
                float4 vb = *reinterpret_cast<const float4*>(x2 + idx);
                sa[IX(i4 + 0)] = va.x; sa[IX(i4 + 1)] = va.y;
                sa[IX(i4 + 2)] = va.z; sa[IX(i4 + 3)] = va.w;
                sb[IX(i4 + 0)] = vb.x; sb[IX(i4 + 1)] = vb.y;
                sb[IX(i4 + 2)] = vb.z; sb[IX(i4 + 3)] = vb.w;
            } else {
                #pragma unroll
                for (int e = 0; e < 4; e++) {
                    int i = i4 + e;
                    if (i < STAGE) {
                        int id = c0 + i;
                        float a = 0.f, b = 0.f;
                        if (id < L) { a = x1[id]; b = x2[id]; }
                        sa[IX(i)] = a; sb[IX(i)] = b;
                    }
                }
            }
        }
        __syncthreads();

        // ---- initial 100-tap window ----
        float s1 = 0.f, s2 = 0.f, s11 = 0.f, s22 = 0.f, s12 = 0.f;
        #pragma unroll 10
        for (int i = 0; i < WSZ; i++) {
            float a = sa[IX(base + i)], b = sb[IX(base + i)];
            s1 += a; s2 += b; s11 += a * a; s22 += b * b; s12 += a * b;
        }

        // ---- slide across KPT outputs; accumulate column partials ----
        #pragma unroll
        for (int k = 0; k < KPT; k++) {
            float cov = s12 - s1 * s2 * invw;
            float v1  = s11 - s1 * s1 * invw;
            float v2  = s22 - s2 * s2 * invw;
            float c   = cov * rsqrtf(v1 * v2);
            rs[IXH(base + k)] = __float2half_rn(c);
            acc[k] += c;                    // NaN only where j >= NOUT (never stored)
            if (k + 1 < KPT) {
                float an = sa[IX(base + WSZ + k)], bn = sb[IX(base + WSZ + k)];
                float ao = sa[IX(base + k)],       bo = sb[IX(base + k)];
                s1  += an - ao;
                s2  += bn - bo;
                s11 += an * an - ao * ao;
                s22 += bn * bn - bo * bo;
                s12 += an * bn - ao * bo;
            }
        }
        __syncthreads();   // rs ready; sa/sb reads done -> safe to restage next row

        // ---- coalesced half store of this row's chunk ----
        __half* __restrict__ orow = g_corr_h + (size_t)row * NOUT;
        for (int i = threadIdx.x; i < CHUNK; i += TPB) {
            int j = c0 + i;
            if (j < NOUT) orow[j] = rs[IXH(i)];
        }
        // NOTE: no extra sync needed; next iteration's first sync orders restaging.
        __syncthreads();
    }

    // ---- per-group column partials (each thread writes 32 consecutive floats) ----
    float* __restrict__ prow = g_partial + (size_t)grp * NOUT;
    #pragma unroll
    for (int k = 0; k < KPT; k++) {
        int j = c0 + base + k;
        if (j < NOUT) prow[j] = acc[k];
    }
}

// K2: collapse 64 group partials -> avg.
__global__ __launch_bounds__(256) void avg_kernel() {
    int c = blockIdx.x * blockDim.x + threadIdx.x;
    if (c >= NOUT) return;
    float s = 0.f;
    #pragma unroll
    for (int g = 0; g < GROUPS; g++) s += g_partial[g * NOUT + c];
    g_avg[c] = s * (1.0f / (float)B);
}

// K3: out = relu(corr - avg). 8 elements/thread, linear indexing
// (TOTAL divisible by 8 -> float4 load of 8 halves always aligned).
__global__ __launch_bounds__(256) void final_kernel(float* __restrict__ out) {
    size_t g  = (size_t)blockIdx.x * blockDim.x + threadIdx.x;
    size_t i0 = g * 8;
    if (i0 >= TOTAL) return;

    uint4 raw = *reinterpret_cast<const uint4*>(g_corr_h + i0);
    __half2 h0 = *reinterpret_cast<__half2*>(&raw.x);
    __half2 h1 = *reinterpret_cast<__half2*>(&raw.y);
    __half2 h2 = *reinterpret_cast<__half2*>(&raw.z);
    __half2 h3 = *reinterpret_cast<__half2*>(&raw.w);
    float2 f0 = __half22float2(h0);
    float2 f1 = __half22float2(h1);
    float2 f2 = __half22float2(h2);
    float2 f3 = __half22float2(h3);
    float v[8] = {f0.x, f0.y, f1.x, f1.y, f2.x, f2.y, f3.x, f3.y};

    int c = (int)(i0 % NOUT);
    float o[8];
    #pragma unroll
    for (int e = 0; e < 8; e++) {
        float r = v[e] - g_avg[c];
        o[e] = r > 0.f ? r : 0.f;
        if (++c == NOUT) c = 0;
    }

    float4* po = reinterpret_cast<float4*>(out + i0);
    po[0] = make_float4(o[0], o[1], o[2], o[3]);
    po[1] = make_float4(o[4], o[5], o[6], o[7]);
}

extern "C" void kernel_launch(void* const* d_in, const int* in_sizes, int n_in,
                              void* d_out, int out_size) {
    const float* x = (const float*)d_in[0];
    float* out = (float*)d_out;

    dim3 g1(NCHUNK, GROUPS);
    corr_fused_kernel<<<g1, TPB>>>(x);

    avg_kernel<<<(NOUT + 255) / 256, 256>>>();

    size_t nv8 = TOTAL / 8;
    final_kernel<<<(unsigned)((nv8 + 255) / 256), 256>>>(out);
}

// round 12
// speedup vs baseline: 1.2227x; 1.2227x over previous
#include <cuda_runtime.h>
#include <cuda_fp16.h>

#define B    512
#define L    32768
#define WSZ  100                 // WINDOW*3 - 2
#define NOUT (L - WSZ + 1)       // 32669
#define TPB  128
#define KPT  32
#define CHUNK (TPB * KPT)        // 4096 outputs per block
#define NCHUNK 8                 // ceil(NOUT/CHUNK)
#define STAGE (CHUNK + WSZ - 1)  // 4195 staged inputs
#define RGROUPS 8
#define ROWS_PER_G (B / RGROUPS) // 64

// float staging: 4-float pad per 32-group. Stride-32 float4 accesses are
// conflict-free (lane t starts at bank 4t mod 32; 8-lane phases cover all
// banks) and 4-aligned vectors never straddle a pad.
#define IX4(i)  ((i) + (((i) >> 5) << 2))
// Round up to multiple of 4 floats so consecutive shared arrays stay 16B-aligned.
#define SPAD    ((IX4(STAGE) + 8 + 3) & ~3)
// half staging: pad 1 per 16 -> stride-32 STS.16 at bank 17t mod 32 (conflict-free)
#define IXH(i)  ((i) + ((i) >> 4))
#define HPAD    ((IXH(CHUNK) + 4 + 7) & ~7)

#define TOTAL ((size_t)B * NOUT)

// Scratch (static device arrays)
__device__ __half g_corr_h[TOTAL];
__device__ float  g_partial[RGROUPS * NOUT];
__device__ float  g_avg[NOUT];

// K1: one (row, 4096-col chunk) per block. Exact sliding window, all shared
// traffic vectorized as float4.
__global__ __launch_bounds__(TPB) void corr_kernel(const float* __restrict__ x) {
    __shared__ __align__(16) float  sa[SPAD];
    __shared__ __align__(16) float  sb[SPAD];
    __shared__ __align__(16) __half rs[HPAD];

    const int row = blockIdx.y;
    const int c0  = blockIdx.x * CHUNK;
    const float* __restrict__ x1 = x + (size_t)row * (2 * L);
    const float* __restrict__ x2 = x1 + L;

    // ---- stage: float4 gmem loads -> float4 shared stores ----
    for (int i4 = threadIdx.x * 4; i4 < STAGE; i4 += TPB * 4) {
        int idx = c0 + i4;
        if (i4 + 3 < STAGE && idx + 3 < L) {
            *reinterpret_cast<float4*>(sa + IX4(i4)) = *reinterpret_cast<const float4*>(x1 + idx);
            *reinterpret_cast<float4*>(sb + IX4(i4)) = *reinterpret_cast<const float4*>(x2 + idx);
        } else {
            #pragma unroll
            for (int e = 0; e < 4; e++) {
                int i = i4 + e;
                if (i < STAGE) {
                    int id = c0 + i;
                    float a = 0.f, b = 0.f;
                    if (id < L) { a = x1[id]; b = x2[id]; }
                    sa[IX4(i)] = a; sb[IX4(i)] = b;
                }
            }
        }
    }
    __syncthreads();

    const int base = threadIdx.x * KPT;

    // ---- initial 100-tap window: 25 float4 loads per array ----
    float s1 = 0.f, s2 = 0.f, s11 = 0.f, s22 = 0.f, s12 = 0.f;
    #pragma unroll
    for (int m = 0; m < WSZ / 4; m++) {
        float4 a4 = *reinterpret_cast<const float4*>(sa + IX4(base + 4 * m));
        float4 b4 = *reinterpret_cast<const float4*>(sb + IX4(base + 4 * m));
        s1  += a4.x + a4.y + a4.z + a4.w;
        s2  += b4.x + b4.y + b4.z + b4.w;
        s11 += a4.x * a4.x + a4.y * a4.y + a4.z * a4.z + a4.w * a4.w;
        s22 += b4.x * b4.x + b4.y * b4.y + b4.z * b4.z + b4.w * b4.w;
        s12 += a4.x * b4.x + a4.y * b4.y + a4.z * b4.z + a4.w * b4.w;
    }

    // ---- slide + emit, 8 macro-steps of 4 outputs; vector old/new loads ----
    const float invw = 1.0f / (float)WSZ;
    #pragma unroll
    for (int q = 0; q < KPT / 4; q++) {
        const int k0 = 4 * q;
        float4 oa = *reinterpret_cast<const float4*>(sa + IX4(base + k0));
        float4 ob = *reinterpret_cast<const float4*>(sb + IX4(base + k0));
        float4 na = *reinterpret_cast<const float4*>(sa + IX4(base + WSZ + k0));
        float4 nb = *reinterpret_cast<const float4*>(sb + IX4(base + WSZ + k0));

        float oav[4] = {oa.x, oa.y, oa.z, oa.w};
        float obv[4] = {ob.x, ob.y, ob.z, ob.w};
        float nav[4] = {na.x, na.y, na.z, na.w};
        float nbv[4] = {nb.x, nb.y, nb.z, nb.w};

        #pragma unroll
        for (int e = 0; e < 4; e++) {
            float cov = s12 - s1 * s2 * invw;
            float v1  = s11 - s1 * s1 * invw;
            float v2  = s22 - s2 * s2 * invw;
            rs[IXH(base + k0 + e)] = __float2half_rn(cov * rsqrtf(v1 * v2));
            // slide to next output (last slide's result is dead; reads in-bounds)
            float an = nav[e], bn = nbv[e], ao = oav[e], bo = obv[e];
            s1  += an - ao;
            s2  += bn - bo;
            s11 += an * an - ao * ao;
            s22 += bn * bn - bo * bo;
            s12 += an * bn - ao * bo;
        }
    }
    __syncthreads();

    // ---- coalesced half store ----
    __half* __restrict__ orow = g_corr_h + (size_t)row * NOUT;
    for (int i = threadIdx.x; i < CHUNK; i += TPB) {
        int j = c0 + i;
        if (j < NOUT) orow[j] = rs[IXH(i)];
    }
}

// K2: partial column sums over 64-row groups (coalesced scalar half reads;
// NOUT is odd so half2 row alignment alternates -> keep scalar).
__global__ __launch_bounds__(256) void colsum_kernel() {
    int c = blockIdx.x * blockDim.x + threadIdx.x;
    int g = blockIdx.y;
    if (c >= NOUT) return;
    const __half* __restrict__ p = g_corr_h + (size_t)g * ROWS_PER_G * NOUT + c;
    float s = 0.f;
    #pragma unroll
    for (int r = 0; r < ROWS_PER_G; r++) s += __half2float(p[(size_t)r * NOUT]);
    g_partial[g * NOUT + c] = s;
}

// K2b: collapse partials -> avg.
__global__ __launch_bounds__(256) void avg_kernel() {
    int c = blockIdx.x * blockDim.x + threadIdx.x;
    if (c >= NOUT) return;
    float s = 0.f;
    #pragma unroll
    for (int g = 0; g < RGROUPS; g++) s += g_partial[g * NOUT + c];
    g_avg[c] = s * (1.0f / (float)B);
}

// K3: out = relu(corr - avg). 8 elements/thread, linear indexing
// (TOTAL divisible by 8 -> uint4 load of 8 halves always aligned).
__global__ __launch_bounds__(256) void final_kernel(float* __restrict__ out) {
    size_t g  = (size_t)blockIdx.x * blockDim.x + threadIdx.x;
    size_t i0 = g * 8;
    if (i0 >= TOTAL) return;

    uint4 raw = *reinterpret_cast<const uint4*>(g_corr_h + i0);
    __half2 h0 = *reinterpret_cast<__half2*>(&raw.x);
    __half2 h1 = *reinterpret_cast<__half2*>(&raw.y);
    __half2 h2 = *reinterpret_cast<__half2*>(&raw.z);
    __half2 h3 = *reinterpret_cast<__half2*>(&raw.w);
    float2 f0 = __half22float2(h0);
    float2 f1 = __half22float2(h1);
    float2 f2 = __half22float2(h2);
    float2 f3 = __half22float2(h3);
    float v[8] = {f0.x, f0.y, f1.x, f1.y, f2.x, f2.y, f3.x, f3.y};

    int c = (int)(i0 % NOUT);
    float o[8];
    #pragma unroll
    for (int e = 0; e < 8; e++) {
        float r = v[e] - g_avg[c];
        o[e] = r > 0.f ? r : 0.f;
        if (++c == NOUT) c = 0;
    }

    float4* po = reinterpret_cast<float4*>(out + i0);
    po[0] = make_float4(o[0], o[1], o[2], o[3]);
    po[1] = make_float4(o[4], o[5], o[6], o[7]);
}

extern "C" void kernel_launch(void* const* d_in, const int* in_sizes, int n_in,
                              void* d_out, int out_size) {
    const float* x = (const float*)d_in[0];
    float* out = (float*)d_out;

    dim3 g1(NCHUNK, B);
    corr_kernel<<<g1, TPB>>>(x);

    dim3 g2((NOUT + 255) / 256, RGROUPS);
    colsum_kernel<<<g2, 256>>>();

    avg_kernel<<<(NOUT + 255) / 256, 256>>>();

    size_t nv8 = TOTAL / 8;
    final_kernel<<<(unsigned)((nv8 + 255) / 256), 256>>>(out);
}